// round 1
// baseline (speedup 1.0000x reference)
#include <cuda_runtime.h>
#include <math.h>

#define N_ 512
#define L_ 65536
#define TWO_PI 6.283185307179586f

// Scratch (allocation-free: __device__ globals)
__device__ float2 d_lam[N_];
__device__ float4 d_t01[N_];   // (t0.re, t0.im, t1.re, t1.im)
__device__ float4 d_t23[N_];   // (t2.re, t2.im, t3.re, t3.im)
__device__ float  d_gscale;    // 2/step
__device__ float2 d_at[L_];    // atRoots
__device__ float2 d_stage[L_]; // FFT intermediate (transposed)

// ---------------------------------------------------------------------------
// Kernel 1: Bc = Vc @ B, term tables, step scale. One block of 512 threads.
// ---------------------------------------------------------------------------
__global__ void prep_kernel(const float* __restrict__ Lre, const float* __restrict__ Lim,
                            const float* __restrict__ pre, const float* __restrict__ pim,
                            const float* __restrict__ qre, const float* __restrict__ qim,
                            const float* __restrict__ Vre, const float* __restrict__ Vim,
                            const float* __restrict__ Ct,  const float* __restrict__ B,
                            const float* __restrict__ log_step) {
    __shared__ float sB[N_];
    int j = threadIdx.x;
    sB[j] = B[j];
    __syncthreads();

    const float* vr = Vre + j * N_;
    const float* vi = Vim + j * N_;
    float br = 0.f, bi = 0.f;
    #pragma unroll 8
    for (int i = 0; i < N_; i++) {
        float b = sB[i];
        br += vr[i] * b;
        bi += vi[i] * b;
    }
    // a0 = conj(Ct_c), a1 = conj(q), b0 = Bc, b1 = p
    float a0r = Ct[2 * j],  a0i = -Ct[2 * j + 1];
    float a1r = qre[j],     a1i = -qim[j];
    float b1r = pre[j],     b1i = pim[j];

    d_t01[j] = make_float4(a0r * br  - a0i * bi,  a0r * bi  + a0i * br,
                           a0r * b1r - a0i * b1i, a0r * b1i + a0i * b1r);
    d_t23[j] = make_float4(a1r * br  - a1i * bi,  a1r * bi  + a1i * br,
                           a1r * b1r - a1i * b1i, a1r * b1i + a1i * b1r);
    d_lam[j] = make_float2(Lre[j], Lim[j]);
    if (j == 0) d_gscale = 2.0f / expf(log_step[0]);
}

// ---------------------------------------------------------------------------
// Kernel 2: Cauchy reductions + low-rank correction -> atRoots[l]
// One thread per l. Tables are warp-uniform loads (L1 broadcast).
// ---------------------------------------------------------------------------
__global__ void cauchy_kernel() {
    int l = blockIdx.x * blockDim.x + threadIdx.x;

    float t = (float)l * (1.0f / (float)L_);
    float s, c;
    sincosf(-TWO_PI * t, &s, &c);          // Omega = (c, s)
    float opr = 1.f + c, opi = s;          // 1 + Omega
    float omr = 1.f - c, omi = -s;         // 1 - Omega
    float pinv = 1.f / (opr * opr + opi * opi);
    float gs = d_gscale;
    float gr = gs * (omr * opr + omi * opi) * pinv;
    float gi = gs * (omi * opr - omr * opi) * pinv;
    float cr = 2.f * opr * pinv;           // cfac = 2/(1+Omega)
    float ci = -2.f * opi * pinv;

    float k00r = 0.f, k00i = 0.f, k01r = 0.f, k01i = 0.f;
    float k10r = 0.f, k10i = 0.f, k11r = 0.f, k11i = 0.f;

    #pragma unroll 8
    for (int j = 0; j < N_; j++) {
        float2 lam = d_lam[j];
        float dr = gr - lam.x;
        float di = gi - lam.y;
        float rinv = 1.f / (dr * dr + di * di);
        float rr = dr * rinv;
        float ri = -di * rinv;
        float4 t01 = d_t01[j];
        float4 t23 = d_t23[j];
        k00r += rr * t01.x - ri * t01.y;  k00i += rr * t01.y + ri * t01.x;
        k01r += rr * t01.z - ri * t01.w;  k01i += rr * t01.w + ri * t01.z;
        k10r += rr * t23.x - ri * t23.y;  k10i += rr * t23.y + ri * t23.x;
        k11r += rr * t23.z - ri * t23.w;  k11i += rr * t23.w + ri * t23.z;
    }

    // atRoots = cfac * (k00 - k01*k10/(1+k11))
    float ddr = 1.f + k11r, ddi = k11i;
    float dinv = 1.f / (ddr * ddr + ddi * ddi);
    float qr = k01r * k10r - k01i * k10i;
    float qi = k01r * k10i + k01i * k10r;
    float qdr = (qr * ddr + qi * ddi) * dinv;
    float qdi = (qi * ddr - qr * ddi) * dinv;
    float ar = k00r - qdr;
    float ai = k00i - qdi;
    d_at[l] = make_float2(cr * ar - ci * ai, cr * ai + ci * ar);
}

// ---------------------------------------------------------------------------
// IFFT via four-step (L = 256 x 256), brute-force 256-pt DFTs.
// out[c + 256 d] = (1/L) sum_a W256^{ad} W_L^{ac} sum_b X[a + 256 b] W256^{bc}
// (W = e^{+2 pi i /.}; ifft sign)
// ---------------------------------------------------------------------------
__global__ void fft_step1() {
    __shared__ float2 col[256];
    __shared__ float2 tw[256];
    int a = blockIdx.x;
    int c = threadIdx.x;

    col[c] = d_at[a + 256 * c];
    {
        float s, cc;
        sincosf(TWO_PI * ((float)c * (1.0f / 256.0f)), &s, &cc);
        tw[c] = make_float2(cc, s);
    }
    __syncthreads();

    float accr = 0.f, acci = 0.f;
    int idx = 0;
    #pragma unroll 8
    for (int b = 0; b < 256; b++) {
        float2 x = col[b];
        float2 w = tw[idx];
        accr += x.x * w.x - x.y * w.y;
        acci += x.x * w.y + x.y * w.x;
        idx = (idx + c) & 255;
    }
    // twiddle W_L^{a*c}
    int m = (a * c) & (L_ - 1);
    float ws, wc;
    sincosf(TWO_PI * ((float)m * (1.0f / (float)L_)), &ws, &wc);
    d_stage[c * 256 + a] = make_float2(accr * wc - acci * ws,
                                       accr * ws + acci * wc);
}

__global__ void fft_step2(float* __restrict__ out) {
    __shared__ float2 col[256];
    __shared__ float2 tw[256];
    int c = blockIdx.x;
    int d = threadIdx.x;

    col[d] = d_stage[c * 256 + d];
    {
        float s, cc;
        sincosf(TWO_PI * ((float)d * (1.0f / 256.0f)), &s, &cc);
        tw[d] = make_float2(cc, s);
    }
    __syncthreads();

    // only the real part of the output is needed
    float acc = 0.f;
    int idx = 0;
    #pragma unroll 8
    for (int a = 0; a < 256; a++) {
        float2 x = col[a];
        float2 w = tw[idx];
        acc += x.x * w.x - x.y * w.y;
        idx = (idx + d) & 255;
    }
    out[c + 256 * d] = acc * (1.0f / (float)L_);
}

// ---------------------------------------------------------------------------
extern "C" void kernel_launch(void* const* d_in, const int* in_sizes, int n_in,
                              void* d_out, int out_size) {
    const float* Lambda_re = (const float*)d_in[0];
    const float* Lambda_im = (const float*)d_in[1];
    const float* p_re      = (const float*)d_in[2];
    const float* p_im      = (const float*)d_in[3];
    const float* q_re      = (const float*)d_in[4];
    const float* q_im      = (const float*)d_in[5];
    const float* Vc_re     = (const float*)d_in[6];
    const float* Vc_im     = (const float*)d_in[7];
    const float* Ct        = (const float*)d_in[8];
    const float* B         = (const float*)d_in[9];
    const float* log_step  = (const float*)d_in[10];
    float* out = (float*)d_out;

    prep_kernel<<<1, N_>>>(Lambda_re, Lambda_im, p_re, p_im, q_re, q_im,
                           Vc_re, Vc_im, Ct, B, log_step);
    cauchy_kernel<<<L_ / 256, 256>>>();
    fft_step1<<<256, 256>>>();
    fft_step2<<<256, 256>>>(out);
}

// round 2
// speedup vs baseline: 4.2891x; 4.2891x over previous
#include <cuda_runtime.h>
#include <math.h>

#define N_ 512
#define L_ 65536
#define TWO_PI 6.283185307179586f

// Scratch (allocation-free: __device__ globals)
__device__ float2 d_lam[N_];
__device__ float4 d_t01[N_];    // (t0.re, t0.im, t1.re, t1.im)
__device__ float4 d_t23[N_];    // (t2.re, t2.im, t3.re, t3.im)
__device__ float  d_gscale;     // 2/step
__device__ float2 d_atT[L_];    // atRoots, TRANSPOSED: atT[a*256 + b] = at[a + 256*b]
__device__ float2 d_stage[L_];  // FFT intermediate

// ---------------------------------------------------------------------------
// Kernel 1: Bc = Vc @ B (one block per row, coalesced), term tables.
// ---------------------------------------------------------------------------
__global__ void prep_kernel(const float* __restrict__ Lre, const float* __restrict__ Lim,
                            const float* __restrict__ pre, const float* __restrict__ pim,
                            const float* __restrict__ qre, const float* __restrict__ qim,
                            const float* __restrict__ Vre, const float* __restrict__ Vim,
                            const float* __restrict__ Ct,  const float* __restrict__ B,
                            const float* __restrict__ log_step) {
    int j = blockIdx.x;
    int t = threadIdx.x;

    const float* vr = Vre + j * N_;
    const float* vi = Vim + j * N_;
    float br = 0.f, bi = 0.f;
    #pragma unroll
    for (int i = t; i < N_; i += 128) {
        float b = __ldg(B + i);
        br += vr[i] * b;
        bi += vi[i] * b;
    }
    #pragma unroll
    for (int o = 16; o > 0; o >>= 1) {
        br += __shfl_down_sync(0xffffffffu, br, o);
        bi += __shfl_down_sync(0xffffffffu, bi, o);
    }
    __shared__ float sr[4], si[4];
    int w = t >> 5;
    if ((t & 31) == 0) { sr[w] = br; si[w] = bi; }
    __syncthreads();
    if (t == 0) {
        br = sr[0] + sr[1] + sr[2] + sr[3];
        bi = si[0] + si[1] + si[2] + si[3];

        // a0 = conj(Ct_c), a1 = conj(q), b0 = Bc, b1 = p
        float a0r = Ct[2 * j],  a0i = -Ct[2 * j + 1];
        float a1r = qre[j],     a1i = -qim[j];
        float b1r = pre[j],     b1i = pim[j];

        d_t01[j] = make_float4(a0r * br  - a0i * bi,  a0r * bi  + a0i * br,
                               a0r * b1r - a0i * b1i, a0r * b1i + a0i * b1r);
        d_t23[j] = make_float4(a1r * br  - a1i * bi,  a1r * bi  + a1i * br,
                               a1r * b1r - a1i * b1i, a1r * b1i + a1i * b1r);
        d_lam[j] = make_float2(Lre[j], Lim[j]);
        if (j == 0) d_gscale = 2.0f / expf(log_step[0]);
    }
}

// ---------------------------------------------------------------------------
// Kernel 2: Cauchy reductions + low-rank correction -> atRoots (transposed).
// Tables in shared memory (broadcast LDS). 2 l-values per thread for ILP.
// ---------------------------------------------------------------------------
__global__ void __launch_bounds__(256) cauchy_kernel() {
    __shared__ float2 slam[N_];
    __shared__ float4 st01[N_];
    __shared__ float4 st23[N_];
    int t = threadIdx.x;
    #pragma unroll
    for (int i = t; i < N_; i += 256) {
        slam[i] = d_lam[i];
        st01[i] = d_t01[i];
        st23[i] = d_t23[i];
    }
    __syncthreads();

    float gs = d_gscale;
    int lbase = blockIdx.x * 512 + t;

    float gr[2], gi[2], cfr[2], cfi[2];
    #pragma unroll
    for (int u = 0; u < 2; u++) {
        int l = lbase + u * 256;
        float s, c;
        sincosf(-TWO_PI * ((float)l * (1.0f / (float)L_)), &s, &c);
        float opr = 1.f + c, opi = s;      // 1 + Omega
        float omr = 1.f - c, omi = -s;     // 1 - Omega
        float pinv = __fdividef(1.f, opr * opr + opi * opi);
        gr[u]  = gs * (omr * opr + omi * opi) * pinv;
        gi[u]  = gs * (omi * opr - omr * opi) * pinv;
        cfr[u] = 2.f * opr * pinv;
        cfi[u] = -2.f * opi * pinv;
    }

    float acc[2][8];
    #pragma unroll
    for (int u = 0; u < 2; u++)
        #pragma unroll
        for (int k = 0; k < 8; k++) acc[u][k] = 0.f;

    #pragma unroll 4
    for (int j = 0; j < N_; j++) {
        float2 lam = slam[j];
        float4 t01 = st01[j];
        float4 t23 = st23[j];
        #pragma unroll
        for (int u = 0; u < 2; u++) {
            float dr = gr[u] - lam.x;
            float di = gi[u] - lam.y;
            float rinv = __fdividef(1.f, dr * dr + di * di);
            float rr = dr * rinv;
            float ri = -di * rinv;
            acc[u][0] += rr * t01.x - ri * t01.y;  acc[u][1] += rr * t01.y + ri * t01.x;
            acc[u][2] += rr * t01.z - ri * t01.w;  acc[u][3] += rr * t01.w + ri * t01.z;
            acc[u][4] += rr * t23.x - ri * t23.y;  acc[u][5] += rr * t23.y + ri * t23.x;
            acc[u][6] += rr * t23.z - ri * t23.w;  acc[u][7] += rr * t23.w + ri * t23.z;
        }
    }

    #pragma unroll
    for (int u = 0; u < 2; u++) {
        int l = lbase + u * 256;
        // atRoots = cfac * (k00 - k01*k10/(1+k11))
        float ddr = 1.f + acc[u][6], ddi = acc[u][7];
        float dinv = __fdividef(1.f, ddr * ddr + ddi * ddi);
        float qr = acc[u][2] * acc[u][4] - acc[u][3] * acc[u][5];
        float qi = acc[u][2] * acc[u][5] + acc[u][3] * acc[u][4];
        float qdr = (qr * ddr + qi * ddi) * dinv;
        float qdi = (qi * ddr - qr * ddi) * dinv;
        float ar = acc[u][0] - qdr;
        float ai = acc[u][1] - qdi;
        // write transposed: atT[a*256 + b], a = l%256, b = l/256
        d_atT[(l & 255) * 256 + (l >> 8)] =
            make_float2(cfr[u] * ar - cfi[u] * ai, cfr[u] * ai + cfi[u] * ar);
    }
}

// ---------------------------------------------------------------------------
// IFFT via four-step (L = 256 x 256), brute-force 256-pt DFTs.
// out[c + 256 d] = (1/L) sum_a W256^{ad} W_L^{ac} sum_b X[a + 256 b] W256^{bc}
// ---------------------------------------------------------------------------
__global__ void fft_step1() {
    __shared__ float2 col[256];
    __shared__ float2 tw[256];
    int a = blockIdx.x;
    int c = threadIdx.x;

    col[c] = d_atT[a * 256 + c];   // coalesced now
    {
        float s, cc;
        sincosf(TWO_PI * ((float)c * (1.0f / 256.0f)), &s, &cc);
        tw[c] = make_float2(cc, s);
    }
    __syncthreads();

    float accr = 0.f, acci = 0.f;
    int idx = 0;
    #pragma unroll 8
    for (int b = 0; b < 256; b++) {
        float2 x = col[b];
        float2 w = tw[idx];
        accr += x.x * w.x - x.y * w.y;
        acci += x.x * w.y + x.y * w.x;
        idx = (idx + c) & 255;
    }
    int m = (a * c) & (L_ - 1);
    float ws, wc;
    sincosf(TWO_PI * ((float)m * (1.0f / (float)L_)), &ws, &wc);
    d_stage[c * 256 + a] = make_float2(accr * wc - acci * ws,
                                       accr * ws + acci * wc);
}

__global__ void fft_step2(float* __restrict__ out) {
    __shared__ float2 col[256];
    __shared__ float2 tw[256];
    int c = blockIdx.x;
    int d = threadIdx.x;

    col[d] = d_stage[c * 256 + d];  // coalesced
    {
        float s, cc;
        sincosf(TWO_PI * ((float)d * (1.0f / 256.0f)), &s, &cc);
        tw[d] = make_float2(cc, s);
    }
    __syncthreads();

    // only the real part of the output is needed
    float acc = 0.f;
    int idx = 0;
    #pragma unroll 8
    for (int a = 0; a < 256; a++) {
        float2 x = col[a];
        float2 w = tw[idx];
        acc += x.x * w.x - x.y * w.y;
        idx = (idx + d) & 255;
    }
    out[c + 256 * d] = acc * (1.0f / (float)L_);
}

// ---------------------------------------------------------------------------
extern "C" void kernel_launch(void* const* d_in, const int* in_sizes, int n_in,
                              void* d_out, int out_size) {
    const float* Lambda_re = (const float*)d_in[0];
    const float* Lambda_im = (const float*)d_in[1];
    const float* p_re      = (const float*)d_in[2];
    const float* p_im      = (const float*)d_in[3];
    const float* q_re      = (const float*)d_in[4];
    const float* q_im      = (const float*)d_in[5];
    const float* Vc_re     = (const float*)d_in[6];
    const float* Vc_im     = (const float*)d_in[7];
    const float* Ct        = (const float*)d_in[8];
    const float* B         = (const float*)d_in[9];
    const float* log_step  = (const float*)d_in[10];
    float* out = (float*)d_out;

    prep_kernel<<<N_, 128>>>(Lambda_re, Lambda_im, p_re, p_im, q_re, q_im,
                             Vc_re, Vc_im, Ct, B, log_step);
    cauchy_kernel<<<L_ / 512, 256>>>();
    fft_step1<<<256, 256>>>();
    fft_step2<<<256, 256>>>(out);
}

// round 3
// speedup vs baseline: 7.3604x; 1.7161x over previous
#include <cuda_runtime.h>
#include <math.h>
#include <stdint.h>

#define N_ 512
#define L_ 65536
#define TWO_PI 6.283185307179586f
#define PI_F   3.14159265358979f

// Scratch (allocation-free: __device__ globals)
__device__ float4 d_jc[N_];        // (lam_im, -lam_re, lam_re^2, 0)
__device__ ulonglong2 d_A01[N_];   // pairs (t0r,t0i),(t1r,t1i)
__device__ ulonglong2 d_A23[N_];   // pairs (t2r,t2i),(t3r,t3i)
__device__ ulonglong2 d_B01[N_];   // pairs (t0i,-t0r),(t1i,-t1r)
__device__ ulonglong2 d_B23[N_];   // pairs (t2i,-t2r),(t3i,-t3r)
__device__ float  d_gscale;        // 2/step
__device__ float2 d_atT[L_];       // atRoots, transposed: atT[a*256+b] = at[a+256b]
__device__ float2 d_stage[L_];     // FFT intermediate

__device__ __forceinline__ uint64_t pack2(float lo, float hi) {
    uint64_t r;
    asm("mov.b64 %0, {%1, %2};" : "=l"(r) : "r"(__float_as_uint(lo)), "r"(__float_as_uint(hi)));
    return r;
}
__device__ __forceinline__ void unpack2(uint64_t p, float& lo, float& hi) {
    uint32_t a, b;
    asm("mov.b64 {%0, %1}, %2;" : "=r"(a), "=r"(b) : "l"(p));
    lo = __uint_as_float(a); hi = __uint_as_float(b);
}
__device__ __forceinline__ uint64_t fma2(uint64_t a, uint64_t b, uint64_t c) {
    uint64_t d;
    asm("fma.rn.f32x2 %0, %1, %2, %3;" : "=l"(d) : "l"(a), "l"(b), "l"(c));
    return d;
}
__device__ __forceinline__ float frcp(float x) {
    float r; asm("rcp.approx.f32 %0, %1;" : "=f"(r) : "f"(x)); return r;
}

// ---------------------------------------------------------------------------
// Kernel 1: Bc = Vc @ B (one block per row, coalesced), packed term tables.
// ---------------------------------------------------------------------------
__global__ void prep_kernel(const float* __restrict__ Lre, const float* __restrict__ Lim,
                            const float* __restrict__ pre, const float* __restrict__ pim,
                            const float* __restrict__ qre, const float* __restrict__ qim,
                            const float* __restrict__ Vre, const float* __restrict__ Vim,
                            const float* __restrict__ Ct,  const float* __restrict__ B,
                            const float* __restrict__ log_step) {
    int j = blockIdx.x;
    int t = threadIdx.x;

    const float* vr = Vre + j * N_;
    const float* vi = Vim + j * N_;
    float br = 0.f, bi = 0.f;
    #pragma unroll
    for (int i = t; i < N_; i += 128) {
        float b = __ldg(B + i);
        br += vr[i] * b;
        bi += vi[i] * b;
    }
    #pragma unroll
    for (int o = 16; o > 0; o >>= 1) {
        br += __shfl_down_sync(0xffffffffu, br, o);
        bi += __shfl_down_sync(0xffffffffu, bi, o);
    }
    __shared__ float sr[4], si[4];
    int w = t >> 5;
    if ((t & 31) == 0) { sr[w] = br; si[w] = bi; }
    __syncthreads();
    if (t == 0) {
        br = sr[0] + sr[1] + sr[2] + sr[3];
        bi = si[0] + si[1] + si[2] + si[3];

        // a0 = conj(Ct_c), a1 = conj(q), b0 = Bc, b1 = p
        float a0r = Ct[2 * j],  a0i = -Ct[2 * j + 1];
        float a1r = qre[j],     a1i = -qim[j];
        float b1r = pre[j],     b1i = pim[j];

        float t0r = a0r * br  - a0i * bi,  t0i = a0r * bi  + a0i * br;
        float t1r = a0r * b1r - a0i * b1i, t1i = a0r * b1i + a0i * b1r;
        float t2r = a1r * br  - a1i * bi,  t2i = a1r * bi  + a1i * br;
        float t3r = a1r * b1r - a1i * b1i, t3i = a1r * b1i + a1i * b1r;

        ulonglong2 v;
        v.x = pack2(t0r, t0i);  v.y = pack2(t1r, t1i);  d_A01[j] = v;
        v.x = pack2(t2r, t2i);  v.y = pack2(t3r, t3i);  d_A23[j] = v;
        v.x = pack2(t0i, -t0r); v.y = pack2(t1i, -t1r); d_B01[j] = v;
        v.x = pack2(t2i, -t2r); v.y = pack2(t3i, -t3r); d_B23[j] = v;

        float lr = Lre[j], li = Lim[j];
        d_jc[j] = make_float4(li, -lr, lr * lr, 0.f);
        if (j == 0) d_gscale = 2.0f / expf(log_step[0]);
    }
}

// ---------------------------------------------------------------------------
// Kernel 2: Cauchy reductions + low-rank correction -> atRoots (transposed).
// g = i*gs*tan(pi*l/L) purely imaginary; c = 1 + i*tan(pi*l/L).
// Packed f32x2 accumulation. 2 l-values per thread for ILP.
// ---------------------------------------------------------------------------
__global__ void __launch_bounds__(256) cauchy_kernel() {
    __shared__ float4     sjc[N_];
    __shared__ ulonglong2 sA01[N_];
    __shared__ ulonglong2 sA23[N_];
    __shared__ ulonglong2 sB01[N_];
    __shared__ ulonglong2 sB23[N_];
    int t = threadIdx.x;
    #pragma unroll
    for (int i = t; i < N_; i += 256) {
        sjc[i]  = d_jc[i];
        sA01[i] = d_A01[i];
        sA23[i] = d_A23[i];
        sB01[i] = d_B01[i];
        sB23[i] = d_B23[i];
    }
    __syncthreads();

    float gs = d_gscale;
    int lbase = blockIdx.x * 512 + t;

    float tanv[2], gi[2];
    #pragma unroll
    for (int u = 0; u < 2; u++) {
        int l = lbase + u * 256;
        float s, c;
        sincosf(PI_F * ((float)l * (1.0f / (float)L_)), &s, &c);
        tanv[u] = __fdividef(s, c);
        gi[u] = gs * tanv[u];
    }

    uint64_t acc[2][4];   // (k00),(k01),(k10),(k11) as (re,im) pairs
    #pragma unroll
    for (int u = 0; u < 2; u++)
        #pragma unroll
        for (int k = 0; k < 4; k++) acc[u][k] = 0ull;

    #pragma unroll 4
    for (int j = 0; j < N_; j++) {
        float4 jc = sjc[j];
        ulonglong2 A01 = sA01[j];
        ulonglong2 A23 = sA23[j];
        ulonglong2 B01 = sB01[j];
        ulonglong2 B23 = sB23[j];
        #pragma unroll
        for (int u = 0; u < 2; u++) {
            float di   = gi[u] - jc.x;             // gi - lam_im
            float n    = fmaf(di, di, jc.z);       // di^2 + lam_re^2
            float rinv = frcp(n);
            float rr   = jc.y * rinv;              // (-lam_re) * rinv
            float ri2  = di * rinv;                //  di * rinv
            uint64_t brr = pack2(rr, rr);
            uint64_t bri = pack2(ri2, ri2);
            acc[u][0] = fma2(brr, A01.x, acc[u][0]);
            acc[u][0] = fma2(bri, B01.x, acc[u][0]);
            acc[u][1] = fma2(brr, A01.y, acc[u][1]);
            acc[u][1] = fma2(bri, B01.y, acc[u][1]);
            acc[u][2] = fma2(brr, A23.x, acc[u][2]);
            acc[u][2] = fma2(bri, B23.x, acc[u][2]);
            acc[u][3] = fma2(brr, A23.y, acc[u][3]);
            acc[u][3] = fma2(bri, B23.y, acc[u][3]);
        }
    }

    #pragma unroll
    for (int u = 0; u < 2; u++) {
        int l = lbase + u * 256;
        float k00r, k00i, k01r, k01i, k10r, k10i, k11r, k11i;
        unpack2(acc[u][0], k00r, k00i);
        unpack2(acc[u][1], k01r, k01i);
        unpack2(acc[u][2], k10r, k10i);
        unpack2(acc[u][3], k11r, k11i);
        // atRoots = (1 + i*tan) * (k00 - k01*k10/(1+k11))
        float ddr = 1.f + k11r, ddi = k11i;
        float dinv = __fdividef(1.f, ddr * ddr + ddi * ddi);
        float qr = k01r * k10r - k01i * k10i;
        float qi = k01r * k10i + k01i * k10r;
        float qdr = (qr * ddr + qi * ddi) * dinv;
        float qdi = (qi * ddr - qr * ddi) * dinv;
        float ar = k00r - qdr;
        float ai = k00i - qdi;
        float tv = tanv[u];
        d_atT[(l & 255) * 256 + (l >> 8)] =
            make_float2(ar - tv * ai, ai + tv * ar);
    }
}

// ---------------------------------------------------------------------------
// IFFT via four-step (L = 256 x 256), each 256-pt DFT done radix-16 x 16.
// out[c + 256 d] = (1/L) sum_a W256^{ad} W_L^{ac} sum_b X[a + 256 b] W256^{bc}
// ---------------------------------------------------------------------------
__global__ void __launch_bounds__(256) fft_step1() {
    __shared__ float2 sx[256];
    __shared__ float2 sw[256];       // w[k] = e^{+2pi i k/256}
    __shared__ float2 sz[16 * 17];   // padded to kill bank conflicts
    int a = blockIdx.x, t = threadIdx.x;

    sx[t] = d_atT[a * 256 + t];
    {
        float s, c;
        sincosf(TWO_PI * ((float)t * (1.0f / 256.0f)), &s, &c);
        sw[t] = make_float2(c, s);
    }
    __syncthreads();

    // Stage A: inner[b1][c1] = sum_b2 x[b1+16b2] W16^{b2 c1}, * W256^{b1 c1}
    {
        int b1 = t & 15, c1 = t >> 4;
        float xr = 0.f, xi = 0.f;
        #pragma unroll
        for (int b2 = 0; b2 < 16; b2++) {
            float2 x = sx[b1 + 16 * b2];
            float2 w = sw[(16 * b2 * c1) & 255];
            xr += x.x * w.x - x.y * w.y;
            xi += x.x * w.y + x.y * w.x;
        }
        float2 tw = sw[b1 * c1];
        sz[b1 * 17 + c1] = make_float2(xr * tw.x - xi * tw.y,
                                       xr * tw.y + xi * tw.x);
    }
    __syncthreads();

    // Stage B: Y[c1+16c2] = sum_b1 z[b1][c1] W16^{b1 c2};   c1+16c2 == t
    {
        int c1 = t & 15, c2 = t >> 4;
        float yr = 0.f, yi = 0.f;
        #pragma unroll
        for (int b1 = 0; b1 < 16; b1++) {
            float2 z = sz[b1 * 17 + c1];
            float2 w = sw[(16 * b1 * c2) & 255];
            yr += z.x * w.x - z.y * w.y;
            yi += z.x * w.y + z.y * w.x;
        }
        int m = (a * t) & (L_ - 1);
        float ws, wc;
        sincosf(TWO_PI * ((float)m * (1.0f / (float)L_)), &ws, &wc);
        d_stage[t * 256 + a] = make_float2(yr * wc - yi * ws,
                                           yr * ws + yi * wc);
    }
}

__global__ void __launch_bounds__(256) fft_step2(float* __restrict__ out) {
    __shared__ float2 sx[256];
    __shared__ float2 sw[256];
    __shared__ float2 sz[16 * 17];
    int c = blockIdx.x, t = threadIdx.x;

    sx[t] = d_stage[c * 256 + t];
    {
        float s, cc;
        sincosf(TWO_PI * ((float)t * (1.0f / 256.0f)), &s, &cc);
        sw[t] = make_float2(cc, s);
    }
    __syncthreads();

    {
        int a1 = t & 15, d1 = t >> 4;
        float xr = 0.f, xi = 0.f;
        #pragma unroll
        for (int a2 = 0; a2 < 16; a2++) {
            float2 x = sx[a1 + 16 * a2];
            float2 w = sw[(16 * a2 * d1) & 255];
            xr += x.x * w.x - x.y * w.y;
            xi += x.x * w.y + x.y * w.x;
        }
        float2 tw = sw[a1 * d1];
        sz[a1 * 17 + d1] = make_float2(xr * tw.x - xi * tw.y,
                                       xr * tw.y + xi * tw.x);
    }
    __syncthreads();

    {
        int d1 = t & 15, d2 = t >> 4;
        float yr = 0.f;   // only real part needed
        #pragma unroll
        for (int a1 = 0; a1 < 16; a1++) {
            float2 z = sz[a1 * 17 + d1];
            float2 w = sw[(16 * a1 * d2) & 255];
            yr += z.x * w.x - z.y * w.y;
        }
        out[c + 256 * t] = yr * (1.0f / (float)L_);
    }
}

// ---------------------------------------------------------------------------
extern "C" void kernel_launch(void* const* d_in, const int* in_sizes, int n_in,
                              void* d_out, int out_size) {
    const float* Lambda_re = (const float*)d_in[0];
    const float* Lambda_im = (const float*)d_in[1];
    const float* p_re      = (const float*)d_in[2];
    const float* p_im      = (const float*)d_in[3];
    const float* q_re      = (const float*)d_in[4];
    const float* q_im      = (const float*)d_in[5];
    const float* Vc_re     = (const float*)d_in[6];
    const float* Vc_im     = (const float*)d_in[7];
    const float* Ct        = (const float*)d_in[8];
    const float* B         = (const float*)d_in[9];
    const float* log_step  = (const float*)d_in[10];
    float* out = (float*)d_out;

    prep_kernel<<<N_, 128>>>(Lambda_re, Lambda_im, p_re, p_im, q_re, q_im,
                             Vc_re, Vc_im, Ct, B, log_step);
    cauchy_kernel<<<L_ / 512, 256>>>();
    fft_step1<<<256, 256>>>();
    fft_step2<<<256, 256>>>(out);
}